// round 17
// baseline (speedup 1.0000x reference)
#include <cuda_runtime.h>
#include <cuda_bf16.h>
#include <cstdint>

// ----------------------------------------------------------------------------
// SpatialFeatureExtractor — FFMA f32x2, double-buffered, dual-parity B (R16)
// + R17: operand-reuse-friendly FMA ordering.
// The R16 inner loop alternated rav.x / rav.y as multiplier each instruction;
// FFMA2 then reads 3 distinct even + 3 distinct odd regs -> RF-bank rt=3
// (ceiling ~85 MAC/cyc/SM; we measured 73). Splitting into two 13-long runs
// with a SHARED multiplier register enables the operand reuse cache -> rt=2
// (ceiling 128 MAC/cyc/SM). Per-accumulator op order unchanged -> bit-identical.
// ----------------------------------------------------------------------------

#define EPSV 1e-5f
constexpr int L  = 520;
constexpr int LP = 528;
constexpr int NS = 1024;

__device__ __align__(16) __nv_bfloat16 g_h1[(size_t)NS * 128 * LP];   // ~138 MB
__device__ __align__(16) __nv_bfloat16 g_h2[(size_t)NS * 256 * LP];   // ~277 MB
__device__ __align__(16) float g_wT2[8 * 48 * 256];    // [chunk][j][c2] CIN=128
__device__ __align__(16) float g_wT3[16 * 48 * 256];   // [chunk][j][c2] CIN=256

__device__ __forceinline__ void dfma2(unsigned long long &d,
                                      unsigned long long a,
                                      unsigned long long b) {
    asm("fma.rn.f32x2 %0, %1, %2, %0;" : "+l"(d) : "l"(a), "l"(b));
}
__device__ __forceinline__ uint32_t smem_u32(const void* p) {
    uint32_t a;
    asm("{ .reg .u64 t; cvta.to.shared.u64 t, %1; cvt.u32.u64 %0, t; }" : "=r"(a) : "l"(p));
    return a;
}
#define CPA16(DST, SRC)                                                       \
    asm volatile("cp.async.cg.shared.global [%0], [%1], 16;" :: "r"(DST), "l"(SRC))
#define CP_COMMIT() asm volatile("cp.async.commit_group;" ::: "memory")
#define CP_WAIT0()  asm volatile("cp.async.wait_group 0;" ::: "memory")

// ----------------------------------------------------------------------------
// Prep: transpose weights into tile layout g_wT[chunk][j][c2]
// ----------------------------------------------------------------------------
__global__ void k_prep_w(const float* __restrict__ w2, const float* __restrict__ w3)
{
    int i = blockIdx.x * 256 + threadIdx.x;
    if (i < 8 * 48 * 256) {
        int chunk = i / (48 * 256), rem = i % (48 * 256);
        int j = rem >> 8, c2 = rem & 255;
        g_wT2[i] = w2[c2 * 384 + chunk * 48 + j];
    } else {
        int i2 = i - 8 * 48 * 256;
        int chunk = i2 / (48 * 256), rem = i2 % (48 * 256);
        int j = rem >> 8, c2 = rem & 255;
        g_wT3[i2] = w3[c2 * 768 + chunk * 48 + j];
    }
}

// ----------------------------------------------------------------------------
// Layer 1: conv1d(1->128)+BN+ReLU -> g_h1 (bf16, padded rows)   [unchanged]
// ----------------------------------------------------------------------------
__global__ void k_conv1(const float* __restrict__ x,  const float* __restrict__ w1,
                        const float* __restrict__ b1, const float* __restrict__ g1,
                        const float* __restrict__ be1, const float* __restrict__ m1,
                        const float* __restrict__ v1)
{
    __shared__ float xs[L + 2];
    __shared__ __align__(16) __nv_bfloat16 hs[32 * LP];
    __shared__ float cw[128 * 3];
    __shared__ float ca[128], cb[128];

    const int tid = threadIdx.x;
    const int n   = blockIdx.x;

    for (int i = tid; i < L; i += 256) xs[i] = x[(size_t)n * L + i];
    if (tid < 2) xs[L + tid] = 0.f;
    for (int i = tid; i < 128 * 3; i += 256) cw[i] = w1[i];
    if (tid < 128) {
        float a = g1[tid] * rsqrtf(v1[tid] + EPSV);
        ca[tid] = a;
        cb[tid] = (b1[tid] - m1[tid]) * a + be1[tid];
    }
    __syncthreads();

    for (int pass = 0; pass < 4; pass++) {
        const int cl  = tid >> 3;
        const int c   = pass * 32 + cl;
        const int seg = tid & 7;
        const float w0 = cw[c * 3 + 0], wa = cw[c * 3 + 1], wb = cw[c * 3 + 2];
        const float a = ca[c], b = cb[c];
        for (int p = seg * 66; p < seg * 66 + 66; p++) {
            float v;
            if (p == 0 || p > L) {
                v = 0.f;
            } else {
                int l = p - 1;
                float xm = (l > 0)     ? xs[l - 1] : 0.f;
                float xp = (l < L - 1) ? xs[l + 1] : 0.f;
                float y  = w0 * xm + wa * xs[l] + wb * xp;
                v = fmaxf(fmaf(y, a, b), 0.f);
            }
            hs[cl * LP + p] = __float2bfloat16(v);
        }
        __syncthreads();
        uint4*       dstv = reinterpret_cast<uint4*>(g_h1 + ((size_t)n * 128 + pass * 32) * LP);
        const uint4* srcv = reinterpret_cast<const uint4*>(hs);
        for (int i = tid; i < 32 * LP * 2 / 16; i += 256) dstv[i] = srcv[i];
        __syncthreads();
    }
}

// ----------------------------------------------------------------------------
// Kernel B: GEMM-conv, double-buffered, dual-parity B tile.
// Dynamic smem (bytes):
//   [0, 2*25344)       A stages: [st][48 j][132 floats]
//   [50688, +2*28672)  B stages: [st][16 r][ Beven 112 f2 | Bodd 112 f2 ]
//   [108032) alpha | [108544) beta | [109056) red    total 109568
// ----------------------------------------------------------------------------
constexpr int AST_B   = 48 * 132 * 4;          // 25344
constexpr int OFF_B   = 2 * AST_B;             // 50688
constexpr int BROWB   = 224 * 8;               // 1792 B per c1 row
constexpr int BST_B   = 16 * BROWB;            // 28672
constexpr int OFF_AL  = OFF_B + 2 * BST_B;     // 108032
constexpr int OFF_BE  = OFF_AL + 512;
constexpr int OFF_RED = OFF_BE + 512;
constexpr int SMEM_DYN = OFF_RED + 512;        // 109568

template <int CIN, bool FUSE>
__global__ __launch_bounds__(256, 2)
void k_conv(const float* __restrict__ bb,
            const float* __restrict__ gg, const float* __restrict__ be,
            const float* __restrict__ mm, const float* __restrict__ vv,
            float* __restrict__ out)
{
    constexpr int KC   = 16;
    constexpr int NCH  = CIN / KC;    // 8 or 16
    constexpr int NT   = 104;
    constexpr int ASTR = 132;         // floats

    extern __shared__ __align__(16) char smem[];
    const uint32_t sb = smem_u32(smem);

    const int tid    = threadIdx.x;
    const int n      = blockIdx.x;
    const int c2base = blockIdx.y * 128;
    const int tm     = tid & 31;
    const int tn     = tid >> 5;

    const __nv_bfloat16* __restrict__ src = FUSE ? g_h2 : g_h1;
    const float* __restrict__ gwT = FUSE ? g_wT3 : g_wT2;
    __nv_bfloat16* dst = g_h2;

    float* s_alpha = reinterpret_cast<float*>(smem + OFF_AL);
    float* s_beta  = reinterpret_cast<float*>(smem + OFF_BE);
    float* s_red   = reinterpret_cast<float*>(smem + OFF_RED);

    if (tid < 128) {
        int c2g = c2base + tid;
        float a = gg[c2g] * rsqrtf(vv[c2g] + EPSV);
        s_alpha[tid] = a;
        s_beta[tid]  = (bb[c2g] - mm[c2g]) * a + be[c2g];
        if (FUSE) s_red[tid] = 0.f;
    }
    if (!FUSE) {
        if (tid < 128) {
            __nv_bfloat16* row = dst + ((size_t)n * 256 + c2base + tid) * LP;
            __nv_bfloat16 z = __float2bfloat16(0.f);
            row[0] = z;
#pragma unroll
            for (int p = L + 1; p < LP; p++) row[p] = z;
        }
    }
    float msum[4];
    if (FUSE) { msum[0] = msum[1] = msum[2] = msum[3] = 0.f; }

    // B-loader coordinates (224 threads): row br, 8 positions from p0
    const int br = tid / 14, bu = tid % 14, p0 = bu * 8;
    const bool bOn = (tid < 224);

    // per-warp B window byte offset inside a c1 row (dual parity)
    const int kpos = tn * 13;
    const uint32_t bWin = (tn & 1) ? (uint32_t)(112 + kpos - 1) * 8
                                   : (uint32_t)kpos * 8;

#define A_ISSUE(CH, ST)                                                       \
    do {                                                                      \
        const float* aSrc_ = gwT + (size_t)((CH) * 48) * 256 + c2base;        \
        for (int i_ = tid; i_ < 1536; i_ += 256) {                            \
            int j_ = i_ >> 5, u_ = i_ & 31;                                   \
            CPA16(sb + (ST) * AST_B + (uint32_t)(j_ * ASTR + u_ * 4) * 4,     \
                  aSrc_ + (size_t)j_ * 256 + u_ * 4);                         \
        }                                                                     \
        CP_COMMIT();                                                          \
    } while (0)

#define B_LOAD(CH)                                                            \
    do {                                                                      \
        if (bOn) {                                                            \
            const __nv_bfloat16* sbp_ = src + ((size_t)n * CIN + (CH) * KC) * LP + l0; \
            uint4 t_ = *reinterpret_cast<const uint4*>(sbp_ + (size_t)br * LP + p0); \
            vbx = t_.x; vby = t_.y; vbz = t_.z; vbw = t_.w;                   \
        }                                                                     \
    } while (0)

#define B_STORE(ST)                                                           \
    do {                                                                      \
        if (bOn) {                                                            \
            float2* row_ = reinterpret_cast<float2*>(smem + OFF_B + (ST) * BST_B \
                                                     + br * BROWB);           \
            float2* be_ = row_ + p0;                                          \
            float2* bo_ = row_ + 112 + p0 - 1;                                \
            float l0_, h0_, l1_, h1_, l2_, h2_, l3_, h3_;                     \
            l0_ = __uint_as_float(vbx << 16); h0_ = __uint_as_float(vbx & 0xFFFF0000u); \
            l1_ = __uint_as_float(vby << 16); h1_ = __uint_as_float(vby & 0xFFFF0000u); \
            l2_ = __uint_as_float(vbz << 16); h2_ = __uint_as_float(vbz & 0xFFFF0000u); \
            l3_ = __uint_as_float(vbw << 16); h3_ = __uint_as_float(vbw & 0xFFFF0000u); \
            *reinterpret_cast<float4*>(be_ + 0) = make_float4(l0_, l0_, h0_, h0_); \
            *reinterpret_cast<float4*>(be_ + 2) = make_float4(l1_, l1_, h1_, h1_); \
            *reinterpret_cast<float4*>(be_ + 4) = make_float4(l2_, l2_, h2_, h2_); \
            *reinterpret_cast<float4*>(be_ + 6) = make_float4(l3_, l3_, h3_, h3_); \
            if (p0 > 0) bo_[0] = make_float2(l0_, l0_);                       \
            bo_[1] = make_float2(h0_, h0_);                                   \
            bo_[2] = make_float2(l1_, l1_);                                   \
            bo_[3] = make_float2(h1_, h1_);                                   \
            bo_[4] = make_float2(l2_, l2_);                                   \
            bo_[5] = make_float2(h2_, h2_);                                   \
            bo_[6] = make_float2(l3_, l3_);                                   \
            bo_[7] = make_float2(h3_, h3_);                                   \
        }                                                                     \
    } while (0)

    for (int nt = 0; nt < 5; nt++) {
        const int l0 = nt * NT;
        unsigned long long acc[2][13];
#pragma unroll
        for (int mj = 0; mj < 2; mj++)
#pragma unroll
            for (int ni = 0; ni < 13; ni++) acc[mj][ni] = 0ull;

        uint32_t vbx = 0, vby = 0, vbz = 0, vbw = 0;

        A_ISSUE(0, 0);
        B_LOAD(0);
        B_STORE(0);
        CP_WAIT0();
        __syncthreads();

#pragma unroll 1
        for (int ch = 0; ch < NCH; ch++) {
            const int st = ch & 1;
            if (ch + 1 < NCH) {
                A_ISSUE(ch + 1, st ^ 1);
                B_LOAD(ch + 1);
            }
            const ulonglong2* __restrict__ AsU2 =
                reinterpret_cast<const ulonglong2*>(smem + st * AST_B);
            const char* __restrict__ bStage = smem + OFF_B + st * BST_B + bWin;
#pragma unroll 1
            for (int c1 = 0; c1 < KC; c1++) {
                ulonglong2 rbp[8];
                const ulonglong2* bp =
                    reinterpret_cast<const ulonglong2*>(bStage + c1 * BROWB);
#pragma unroll
                for (int i = 0; i < 8; i++) rbp[i] = bp[i];
#pragma unroll
                for (int t = 0; t < 3; t++) {
                    const int j = c1 * 3 + t;
                    ulonglong2 rav = AsU2[j * (ASTR / 4) + tm];
                    // R17: split mj streams -> 13 consecutive FFMA2 sharing
                    // the multiplier register (operand reuse cache, rt 3->2).
#pragma unroll
                    for (int ni = 0; ni < 13; ni++) {
                        const int wdx = ni + t;
                        unsigned long long bv = (wdx & 1) ? rbp[wdx >> 1].y
                                                          : rbp[wdx >> 1].x;
                        dfma2(acc[0][ni], rav.x, bv);
                    }
#pragma unroll
                    for (int ni = 0; ni < 13; ni++) {
                        const int wdx = ni + t;
                        unsigned long long bv = (wdx & 1) ? rbp[wdx >> 1].y
                                                          : rbp[wdx >> 1].x;
                        dfma2(acc[1][ni], rav.y, bv);
                    }
                }
            }
            if (ch + 1 < NCH) {
                B_STORE(st ^ 1);
                CP_WAIT0();
            }
            __syncthreads();
        }

        // --- epilogue for this N tile (unchanged) ---
#pragma unroll
        for (int mj = 0; mj < 2; mj++) {
            const int c2l0 = tm * 4 + mj * 2;
            const float a0 = s_alpha[c2l0],     b0 = s_beta[c2l0];
            const float a1 = s_alpha[c2l0 + 1], b1 = s_beta[c2l0 + 1];
            if (!FUSE) {
                __nv_bfloat16* r0 = dst + ((size_t)n * 256 + c2base + c2l0) * LP
                                        + l0 + tn * 13 + 1;
                __nv_bfloat16* r1 = r0 + LP;
#pragma unroll
                for (int ni = 0; ni < 13; ni++) {
                    float lo = __uint_as_float((unsigned)(acc[mj][ni] & 0xffffffffu));
                    float hi = __uint_as_float((unsigned)(acc[mj][ni] >> 32));
                    r0[ni] = __float2bfloat16(fmaxf(fmaf(lo, a0, b0), 0.f));
                    r1[ni] = __float2bfloat16(fmaxf(fmaf(hi, a1, b1), 0.f));
                }
            } else {
                float s0 = 0.f, s1 = 0.f;
#pragma unroll
                for (int ni = 0; ni < 13; ni++) {
                    float lo = __uint_as_float((unsigned)(acc[mj][ni] & 0xffffffffu));
                    float hi = __uint_as_float((unsigned)(acc[mj][ni] >> 32));
                    s0 += fmaxf(fmaf(lo, a0, b0), 0.f);
                    s1 += fmaxf(fmaf(hi, a1, b1), 0.f);
                }
                msum[mj * 2 + 0] += s0;
                msum[mj * 2 + 1] += s1;
            }
        }
    }
#undef A_ISSUE
#undef B_LOAD
#undef B_STORE

    if (FUSE) {
        __syncthreads();
#pragma unroll
        for (int q = 0; q < 4; q++) atomicAdd(&s_red[tm * 4 + q], msum[q]);
        __syncthreads();
        if (tid < 128)
            out[(size_t)n * 256 + c2base + tid] = s_red[tid] * (1.f / 520.f);
    }
}

// ----------------------------------------------------------------------------
// launch
// ----------------------------------------------------------------------------
extern "C" void kernel_launch(void* const* d_in, const int* in_sizes, int n_in,
                              void* d_out, int out_size)
{
    (void)in_sizes; (void)n_in; (void)out_size;
    const float* x   = (const float*)d_in[0];
    const float* w1  = (const float*)d_in[1];
    const float* b1  = (const float*)d_in[2];
    const float* w2  = (const float*)d_in[3];
    const float* b2  = (const float*)d_in[4];
    const float* w3  = (const float*)d_in[5];
    const float* b3  = (const float*)d_in[6];
    const float* g1  = (const float*)d_in[7];
    const float* be1 = (const float*)d_in[8];
    const float* m1  = (const float*)d_in[9];
    const float* v1  = (const float*)d_in[10];
    const float* g2  = (const float*)d_in[11];
    const float* be2 = (const float*)d_in[12];
    const float* m2  = (const float*)d_in[13];
    const float* v2  = (const float*)d_in[14];
    const float* g3  = (const float*)d_in[15];
    const float* be3 = (const float*)d_in[16];
    const float* m3  = (const float*)d_in[17];
    const float* v3  = (const float*)d_in[18];
    float* out = (float*)d_out;

    cudaFuncSetAttribute(k_conv<128, false>,
                         cudaFuncAttributeMaxDynamicSharedMemorySize, SMEM_DYN);
    cudaFuncSetAttribute(k_conv<256, true>,
                         cudaFuncAttributeMaxDynamicSharedMemorySize, SMEM_DYN);

    k_prep_w<<<(8 * 48 * 256 + 16 * 48 * 256) / 256, 256>>>(w2, w3);
    k_conv1<<<NS, 256>>>(x, w1, b1, g1, be1, m1, v1);
    k_conv<128, false><<<dim3(NS, 2), 256, SMEM_DYN>>>(b2, g2, be2, m2, v2, nullptr);
    k_conv<256, true ><<<dim3(NS, 2), 256, SMEM_DYN>>>(b3, g3, be3, m3, v3, out);
}